// round 13
// baseline (speedup 1.0000x reference)
#include <cuda_runtime.h>
#include <cuda_fp16.h>

#define NMAX 100000
#define EMAX 1600000
#define HDIM 64
#define NGROUP 8

// ---------------- device scratch (no allocation allowed) --------------------
__device__ __align__(256) __half g_h16[NMAX * HDIM];  // fp16 mirror for gathers
__device__ __align__(256) float g_hB[NMAX * HDIM];    // fp32 gather output
__device__ float g_s[NMAX];
__device__ float g_d[NMAX];
__device__ int   g_cnt[NMAX + 1];     // histogram, later scatter cursor
__device__ int   g_offs[NMAX + 1];    // CSR row offsets (by dst)
__device__ int   g_blksum[256];
__device__ int   g_csr[EMAX];         // src indices sorted by dst
__device__ float g_vnsum[NGROUP * HDIM];

// ---------------------------------------------------------------------------
// CSR build: zero -> histogram -> scanA -> scanC(+blk prefix) -> scatter
// ---------------------------------------------------------------------------
__global__ void zero_kernel(int N) {
    int i = blockIdx.x * blockDim.x + threadIdx.x;
    if (i <= N) g_cnt[i] = 0;
    if (i < NGROUP * HDIM) g_vnsum[i] = 0.f;
}

__global__ void hist_kernel(const int* __restrict__ ei, int E) {
    int e = blockIdx.x * blockDim.x + threadIdx.x;
    if (e < E) atomicAdd(&g_cnt[ei[E + e]], 1);
}

// per-block exclusive scan of g_cnt (1024 elements / block of 256 threads)
__global__ void scanA_kernel(int N) {
    __shared__ int wsum[8];
    int t = threadIdx.x;
    int base = blockIdx.x * 1024;
    int v[4]; int s = 0;
#pragma unroll
    for (int j = 0; j < 4; j++) {
        int idx = base + t * 4 + j;
        v[j] = (idx < N) ? g_cnt[idx] : 0;
        s += v[j];
    }
    int lane = t & 31, wid = t >> 5;
    int inc = s;
#pragma unroll
    for (int o = 1; o < 32; o <<= 1) {
        int y = __shfl_up_sync(0xffffffffu, inc, o);
        if (lane >= o) inc += y;
    }
    if (lane == 31) wsum[wid] = inc;
    __syncthreads();
    if (t < 8) {
        int x = wsum[t];
#pragma unroll
        for (int o = 1; o < 8; o <<= 1) {
            int y = __shfl_up_sync(0xffu, x, o);
            if (t >= o) x += y;
        }
        wsum[t] = x;
    }
    __syncthreads();
    int excl = inc - s + (wid > 0 ? wsum[wid - 1] : 0);
#pragma unroll
    for (int j = 0; j < 4; j++) {
        int idx = base + t * 4 + j;
        if (idx < N) g_offs[idx] = excl;
        excl += v[j];
    }
    if (t == 255) g_blksum[blockIdx.x] = wsum[7];
}

// adds cross-block prefix (computed in-kernel by warp 0) and finalizes offsets
__global__ void scanC_kernel(int N, int E) {
    __shared__ int sbase;
    int myblk = (blockIdx.x * 256) >> 10;
    if (threadIdx.x < 32) {
        int acc = 0;
        for (int j = threadIdx.x; j < myblk; j += 32) acc += g_blksum[j];
#pragma unroll
        for (int o = 16; o >= 1; o >>= 1) acc += __shfl_xor_sync(0xffffffffu, acc, o);
        if (threadIdx.x == 0) sbase = acc;
    }
    __syncthreads();
    int i = blockIdx.x * 256 + threadIdx.x;
    if (i < N) {
        int o = g_offs[i] + sbase;
        g_offs[i] = o;
        g_cnt[i] = o;   // scatter cursor
    }
    if (i == 0) g_offs[N] = E;
}

__global__ void scatter_kernel(const int* __restrict__ ei, int E) {
    int e = blockIdx.x * blockDim.x + threadIdx.x;
    if (e >= E) return;
    int src = ei[e];
    int dst = ei[E + e];
    int pos = atomicAdd(&g_cnt[dst], 1);
    g_csr[pos] = src;
}

// ---------------------------------------------------------------------------
// Layer 0 linear: h = x(N,3) @ W0(3,64) -> g_h16; also s = h.as, d = h.ad
// ---------------------------------------------------------------------------
__global__ void lin0_kernel(const float* __restrict__ x,
                            const float* __restrict__ W0,
                            const float* __restrict__ as0,
                            const float* __restrict__ ad0, int N) {
    __shared__ float Ws[3 * 64];
    __shared__ float hs[64][65];
    int t = threadIdx.x;
    int c = t & 63, r = t >> 6;
    int n0 = blockIdx.x * 64;
    if (t < 192) Ws[t] = W0[t];
    __syncthreads();
#pragma unroll
    for (int i = 0; i < 16; i++) {
        int nl = r * 16 + i;
        int n = n0 + nl;
        float acc = 0.f;
        if (n < N) {
            float x0 = x[n * 3 + 0], x1 = x[n * 3 + 1], x2 = x[n * 3 + 2];
            acc = x0 * Ws[c] + x1 * Ws[64 + c] + x2 * Ws[128 + c];
            g_h16[n * 64 + c] = __float2half_rn(acc);
        }
        hs[nl][c] = acc;
    }
    __syncthreads();
    if (t < 64) {
        int n = n0 + t;
        if (n < N) {
            float sv = 0.f, dv = 0.f;
#pragma unroll
            for (int k = 0; k < 64; k++) {
                float hv = hs[t][k];
                sv += hv * as0[k];
                dv += hv * ad0[k];
            }
            g_s[n] = sv;
            g_d[n] = dv;
        }
    }
}

// ---------------------------------------------------------------------------
// Gather attention pass (g_h16 -> g_hB): one warp per dst node.
// Staging as before (each lane computes p for one edge; entries >= cnt carry
// pv=0). Broadcast phase: 4 QUARTER-warps (8 lanes) process 4 different
// staged edges of the SAME node; each lane covers 16B (8 halves) of the row
// via LDG.128 -> one LDG.128/LDS.64 serves FOUR edges. Warp-uniform control
// flow. Quarters merged by shfl_xor(8) + shfl_xor(16).
// (max-shift skipped: softmax shift-invariant, logits are O(0.1))
// ---------------------------------------------------------------------------
__global__ void gather_kernel(const float* __restrict__ bias, int N) {
    __shared__ int2 stage[8][32];
    int w = (blockIdx.x * blockDim.x + threadIdx.x) >> 5;
    int lane = threadIdx.x & 31;
    int wl = threadIdx.x >> 5;
    if (w >= N) return;
    int dst = w;
    int l8 = lane & 7;           // lane within quarter (16B slice index)
    int q = lane >> 3;           // quarter id 0..3
    float dv = g_d[dst];
    // self loop
    float lg = g_s[dst] + dv;
    lg = lg > 0.f ? lg : 0.2f * lg;
    float pself = __expf(lg);
    float a[8];
#pragma unroll
    for (int k = 0; k < 8; k++) a[k] = 0.f;
    if (q == 0) {
        uint4 r = *(const uint4*)(g_h16 + dst * 64 + l8 * 8);
        const __half2* hp = (const __half2*)&r;
#pragma unroll
        for (int k = 0; k < 4; k++) {
            float2 f = __half22float2(hp[k]);
            a[2 * k]     = pself * f.x;
            a[2 * k + 1] = pself * f.y;
        }
    }
    float denl = (lane == 0) ? pself : 0.f;
    int e0 = g_offs[dst], e1 = g_offs[dst + 1];
    for (int base = e0; base < e1; base += 32) {
        int cnt = e1 - base;
        if (cnt > 32) cnt = 32;
        int idx = 0;
        float pv = 0.f;
        if (lane < cnt) {
            idx = g_csr[base + lane];
            float sv = g_s[idx];
            float l = sv + dv;
            l = l > 0.f ? l : 0.2f * l;
            pv = __expf(l);
        }
        denl += pv;
        stage[wl][lane] = make_int2(idx, __float_as_int(pv));
        __syncwarp();
        int j = 0;
        for (; j + 7 < cnt; j += 8) {     // 8 edges per iter: 2 per quarter
            int2 v0 = stage[wl][j + q];
            int2 v1 = stage[wl][j + 4 + q];
            uint4 r0 = *(const uint4*)(g_h16 + v0.x * 64 + l8 * 8);
            uint4 r1 = *(const uint4*)(g_h16 + v1.x * 64 + l8 * 8);
            float p0 = __int_as_float(v0.y), p1 = __int_as_float(v1.y);
            const __half2* h0 = (const __half2*)&r0;
            const __half2* h1 = (const __half2*)&r1;
#pragma unroll
            for (int k = 0; k < 4; k++) {
                float2 f0 = __half22float2(h0[k]);
                float2 f1 = __half22float2(h1[k]);
                a[2 * k]     += p0 * f0.x + p1 * f1.x;
                a[2 * k + 1] += p0 * f0.y + p1 * f1.y;
            }
        }
        for (; j < cnt; j += 4) {         // padded entries have pv = 0
            int2 v = stage[wl][j + q];
            uint4 r = *(const uint4*)(g_h16 + v.x * 64 + l8 * 8);
            float p = __int_as_float(v.y);
            const __half2* h = (const __half2*)&r;
#pragma unroll
            for (int k = 0; k < 4; k++) {
                float2 f = __half22float2(h[k]);
                a[2 * k]     += p * f.x;
                a[2 * k + 1] += p * f.y;
            }
        }
        __syncwarp();
    }
    // merge the four quarters (same columns)
#pragma unroll
    for (int k = 0; k < 8; k++) {
        a[k] += __shfl_xor_sync(0xffffffffu, a[k], 8);
        a[k] += __shfl_xor_sync(0xffffffffu, a[k], 16);
    }
#pragma unroll
    for (int o = 16; o >= 1; o >>= 1) denl += __shfl_xor_sync(0xffffffffu, denl, o);
    if (q == 0) {
        float inv = 1.f / denl;
        float4 bv0 = *(const float4*)(bias + l8 * 8);
        float4 bv1 = *(const float4*)(bias + l8 * 8 + 4);
        float o0 = a[0] * inv + bv0.x;
        float o1 = a[1] * inv + bv0.y;
        float o2 = a[2] * inv + bv0.z;
        float o3 = a[3] * inv + bv0.w;
        float o4 = a[4] * inv + bv1.x;
        float o5 = a[5] * inv + bv1.y;
        float o6 = a[6] * inv + bv1.z;
        float o7 = a[7] * inv + bv1.w;
        o0 = o0 > 0.f ? o0 : 0.01f * o0;
        o1 = o1 > 0.f ? o1 : 0.01f * o1;
        o2 = o2 > 0.f ? o2 : 0.01f * o2;
        o3 = o3 > 0.f ? o3 : 0.01f * o3;
        o4 = o4 > 0.f ? o4 : 0.01f * o4;
        o5 = o5 > 0.f ? o5 : 0.01f * o5;
        o6 = o6 > 0.f ? o6 : 0.01f * o6;
        o7 = o7 > 0.f ? o7 : 0.01f * o7;
        *(float4*)(g_hB + dst * 64 + l8 * 8)     = make_float4(o0, o1, o2, o3);
        *(float4*)(g_hB + dst * 64 + l8 * 8 + 4) = make_float4(o4, o5, o6, o7);
    }
}

// ---------------------------------------------------------------------------
// Tensor-core GEMM (g_hB -> g_h16): h = x(128,64) @ W(64,64) via
// mma.sync.m16n8k8.f32.f16.f16.f32. Block 256 = 8 warps x 16 nodes.
// ---------------------------------------------------------------------------
__global__ void fin_lin_kernel(const float* __restrict__ W,
                               const float* __restrict__ avs,
                               const float* __restrict__ avd, int N) {
    __shared__ __half xh[128][72];
    __shared__ __half Wt[64][72];
    __shared__ float as_sh[64], ad_sh[64];
    int t = threadIdx.x;
    int n0 = blockIdx.x * 128;
    // W -> fp16 transposed
#pragma unroll
    for (int j = 0; j < 16; j++) {
        int idx = j * 256 + t;
        int k = idx >> 6, n = idx & 63;
        Wt[n][k] = __float2half_rn(W[idx]);
    }
    if (t < 64) { as_sh[t] = avs[t]; ad_sh[t] = avd[t]; }
    // x (fp32 gather output) -> fp16 smem
#pragma unroll
    for (int j = 0; j < 8; j++) {
        int idx = j * 256 + t;            // float4 chunks over 128x64
        int nl = idx >> 4, c4 = (idx & 15) * 4;
        int n = n0 + nl;
        float4 v = (n < N) ? *(const float4*)(g_hB + (long long)n * 64 + c4)
                           : make_float4(0.f, 0.f, 0.f, 0.f);
        *(__half2*)&xh[nl][c4]     = __floats2half2_rn(v.x, v.y);
        *(__half2*)&xh[nl][c4 + 2] = __floats2half2_rn(v.z, v.w);
    }
    __syncthreads();

    int wid = t >> 5, lane = t & 31;
    int g = lane >> 2, tg = lane & 3;
    int nw = wid * 16;                     // warp's node base within block
    float acc[8][4];
#pragma unroll
    for (int i = 0; i < 8; i++)
#pragma unroll
        for (int j = 0; j < 4; j++) acc[i][j] = 0.f;

#pragma unroll
    for (int s = 0; s < 8; s++) {
        unsigned a0 = *(const unsigned*)&xh[nw + g][s * 8 + tg * 2];
        unsigned a1 = *(const unsigned*)&xh[nw + g + 8][s * 8 + tg * 2];
#pragma unroll
        for (int nt = 0; nt < 8; nt++) {
            unsigned b = *(const unsigned*)&Wt[nt * 8 + g][s * 8 + tg * 2];
            asm volatile(
                "mma.sync.aligned.m16n8k8.row.col.f32.f16.f16.f32 "
                "{%0,%1,%2,%3}, {%4,%5}, {%6}, {%0,%1,%2,%3};"
                : "+f"(acc[nt][0]), "+f"(acc[nt][1]),
                  "+f"(acc[nt][2]), "+f"(acc[nt][3])
                : "r"(a0), "r"(a1), "r"(b));
        }
    }

    // s/d dots from fp32 accumulators
    float ps0 = 0.f, ps1 = 0.f, pd0 = 0.f, pd1 = 0.f;
#pragma unroll
    for (int nt = 0; nt < 8; nt++) {
        float2 a = *(const float2*)&as_sh[nt * 8 + tg * 2];
        float2 d = *(const float2*)&ad_sh[nt * 8 + tg * 2];
        ps0 += acc[nt][0] * a.x + acc[nt][1] * a.y;
        ps1 += acc[nt][2] * a.x + acc[nt][3] * a.y;
        pd0 += acc[nt][0] * d.x + acc[nt][1] * d.y;
        pd1 += acc[nt][2] * d.x + acc[nt][3] * d.y;
    }
#pragma unroll
    for (int o = 1; o <= 2; o <<= 1) {
        ps0 += __shfl_xor_sync(0xffffffffu, ps0, o);
        ps1 += __shfl_xor_sync(0xffffffffu, ps1, o);
        pd0 += __shfl_xor_sync(0xffffffffu, pd0, o);
        pd1 += __shfl_xor_sync(0xffffffffu, pd1, o);
    }
    if (tg == 0) {
        int n1 = n0 + nw + g, n2 = n1 + 8;
        if (n1 < N) { g_s[n1] = ps0; g_d[n1] = pd0; }
        if (n2 < N) { g_s[n2] = ps1; g_d[n2] = pd1; }
    }

    // stage fp16 result into this warp's own xh rows, then vectorized copy out
#pragma unroll
    for (int nt = 0; nt < 8; nt++) {
        *(__half2*)&xh[nw + g][nt * 8 + tg * 2]     = __floats2half2_rn(acc[nt][0], acc[nt][1]);
        *(__half2*)&xh[nw + g + 8][nt * 8 + tg * 2] = __floats2half2_rn(acc[nt][2], acc[nt][3]);
    }
    __syncwarp();
#pragma unroll
    for (int j = 0; j < 4; j++) {
        int cid = j * 32 + lane;           // 128 uint4 chunks = 16 rows x 8
        int r = nw + (cid >> 3);
        int c = (cid & 7) * 8;
        uint4 v = *(const uint4*)&xh[r][c];
        int n = n0 + r;
        if (n < N) *(uint4*)(g_h16 + (long long)n * 64 + c) = v;
    }
}

// ---------------------------------------------------------------------------
// Final stage (reads g_hB): out1 = h @ out_w + out_b (4x5 register tile);
// vn run-length pooling (batch sorted). Block: 128 nodes, 128 threads.
// ---------------------------------------------------------------------------
__global__ void fin_last_kernel(const float* __restrict__ out_w,
                                const float* __restrict__ out_b,
                                const int* __restrict__ batch,
                                float* __restrict__ out1, int N) {
    __shared__ float hs[128][65];
    __shared__ float ow[64][20];
    __shared__ float ob[20];
    __shared__ int bsh[128];
    int t = threadIdx.x;
    int n0 = blockIdx.x * 128;
    for (int idx = t; idx < 64 * 20; idx += 128) ow[idx / 20][idx % 20] = out_w[idx];
    if (t < 20) ob[t] = out_b[t];
#pragma unroll
    for (int j = 0; j < 64; j++) {
        int idx = j * 128 + t;
        int nl = idx >> 6, c = idx & 63;
        int n = n0 + nl;
        hs[nl][c] = (n < N) ? g_hB[n * 64 + c] : 0.f;
    }
    {
        int n = n0 + t;
        bsh[t] = (n < N) ? batch[n] : -1;
    }
    __syncthreads();
    int ngq = t >> 2, cgq = t & 3;   // 32 node groups x 4 col groups
    float acc[4][5];
#pragma unroll
    for (int i = 0; i < 4; i++)
#pragma unroll
        for (int j = 0; j < 5; j++) acc[i][j] = ob[cgq * 5 + j];
#pragma unroll 8
    for (int k = 0; k < 64; k++) {
        float wv[5];
#pragma unroll
        for (int j = 0; j < 5; j++) wv[j] = ow[k][cgq * 5 + j];
#pragma unroll
        for (int i = 0; i < 4; i++) {
            float hv = hs[ngq * 4 + i][k];
#pragma unroll
            for (int j = 0; j < 5; j++) acc[i][j] += hv * wv[j];
        }
    }
#pragma unroll
    for (int i = 0; i < 4; i++) {
        int n = n0 + ngq * 4 + i;
        if (n < N) {
#pragma unroll
            for (int j = 0; j < 5; j++) out1[n * 20 + cgq * 5 + j] = acc[i][j];
        }
    }
    // vn pooling: threads 0..63 own one column each, run-length over block
    if (t < 64) {
        int nend = N - n0;
        if (nend > 128) nend = 128;
        if (nend > 0) {
            int curg = bsh[0];
            float run = 0.f;
            for (int nl = 0; nl < nend; nl++) {
                int g = bsh[nl];
                if (g != curg) {
                    atomicAdd(&g_vnsum[curg * 64 + t], run);
                    run = 0.f;
                    curg = g;
                }
                run += hs[nl][t];
            }
            atomicAdd(&g_vnsum[curg * 64 + t], run);
        }
    }
}

// ---------------------------------------------------------------------------
// Virtual-node MLP head: 4 layers on [8,64] -> [8,20]. One block.
// ---------------------------------------------------------------------------
__global__ void vn_mlp_kernel(const float* __restrict__ vn_emb0,
                              const float* __restrict__ w1, const float* __restrict__ bb1,
                              const float* __restrict__ w2, const float* __restrict__ bb2,
                              const float* __restrict__ w3, const float* __restrict__ bb3,
                              const float* __restrict__ w4, const float* __restrict__ bb4,
                              float* __restrict__ outvn) {
    __shared__ float a[NGROUP][64], tmp[NGROUP][64];
    int t = threadIdx.x;  // 512
    int g = t >> 6, c = t & 63;
    a[g][c] = g_vnsum[g * 64 + c] + vn_emb0[c];
    __syncthreads();
    float s = bb1[c];
    for (int k = 0; k < 64; k++) s += a[g][k] * w1[k * 64 + c];
    tmp[g][c] = fmaxf(s, 0.f);
    __syncthreads();
    s = bb2[c];
    for (int k = 0; k < 64; k++) s += tmp[g][k] * w2[k * 64 + c];
    a[g][c] = fmaxf(s, 0.f);
    __syncthreads();
    s = bb3[c];
    for (int k = 0; k < 64; k++) s += a[g][k] * w3[k * 64 + c];
    tmp[g][c] = fmaxf(s, 0.f);
    __syncthreads();
    if (c < 20) {
        s = bb4[c];
        for (int k = 0; k < 64; k++) s += tmp[g][k] * w4[k * 20 + c];
        outvn[g * 20 + c] = fmaxf(s, 0.f);
    }
}

// ---------------------------------------------------------------------------
extern "C" void kernel_launch(void* const* d_in, const int* in_sizes, int n_in,
                              void* d_out, int out_size) {
    const float* x      = (const float*)d_in[0];
    const int*   ei     = (const int*)d_in[1];
    const int*   batch  = (const int*)d_in[2];
    const float* W0     = (const float*)d_in[3];
    const float* as0    = (const float*)d_in[4];
    const float* ad0    = (const float*)d_in[5];
    const float* b0     = (const float*)d_in[6];
    const float* W1     = (const float*)d_in[7];
    const float* as1    = (const float*)d_in[8];
    const float* ad1    = (const float*)d_in[9];
    const float* b1     = (const float*)d_in[10];
    const float* W2     = (const float*)d_in[11];
    const float* as2    = (const float*)d_in[12];
    const float* ad2    = (const float*)d_in[13];
    const float* b2     = (const float*)d_in[14];
    const float* vn_emb0= (const float*)d_in[15];
    const float* m1_w1  = (const float*)d_in[16];
    const float* m1_b1  = (const float*)d_in[17];
    const float* m1_w2  = (const float*)d_in[18];
    const float* m1_b2  = (const float*)d_in[19];
    const float* mf_w1  = (const float*)d_in[20];
    const float* mf_b1  = (const float*)d_in[21];
    const float* mf_w2  = (const float*)d_in[22];
    const float* mf_b2  = (const float*)d_in[23];
    const float* out_w  = (const float*)d_in[24];
    const float* out_b  = (const float*)d_in[25];

    int N = in_sizes[0] / 3;
    int E = in_sizes[1] / 2;
    float* out1 = (float*)d_out;
    float* outvn = out1 + (long long)N * 20;

    int nblk64  = (N + 63) / 64;
    int nblk128 = (N + 127) / 128;
    int eblk    = (E + 255) / 256;
    int NB      = (N + 1023) / 1024;
    int gblk    = (N * 32 + 255) / 256;   // one full warp per node

    // CSR build (graph shared by all 3 layers)
    zero_kernel<<<(N + 256) / 256, 256>>>(N);
    hist_kernel<<<eblk, 256>>>(ei, E);
    scanA_kernel<<<NB, 256>>>(N);
    scanC_kernel<<<(N + 255) / 256, 256>>>(N, E);
    scatter_kernel<<<eblk, 256>>>(ei, E);

    // GNN layers (ping-pong: lin0 -> h16, gather h16->B, fin_lin B->h16)
    lin0_kernel<<<nblk64, 256>>>(x, W0, as0, ad0, N);
    gather_kernel<<<gblk, 256>>>(b0, N);
    fin_lin_kernel<<<nblk128, 256>>>(W1, as1, ad1, N);
    gather_kernel<<<gblk, 256>>>(b1, N);
    fin_lin_kernel<<<nblk128, 256>>>(W2, as2, ad2, N);
    gather_kernel<<<gblk, 256>>>(b2, N);

    // heads (read g_hB)
    fin_last_kernel<<<nblk128, 128>>>(out_w, out_b, batch, out1, N);
    vn_mlp_kernel<<<1, 512>>>(vn_emb0, m1_w1, m1_b1, m1_w2, m1_b2,
                              mf_w1, mf_b1, mf_w2, mf_b2, outvn);
}

// round 15
// speedup vs baseline: 1.0178x; 1.0178x over previous
#include <cuda_runtime.h>
#include <cuda_fp16.h>

#define NMAX 100000
#define EMAX 1600000
#define HDIM 64
#define NGROUP 8

// ---------------- device scratch (no allocation allowed) --------------------
__device__ __align__(256) __half g_h16[NMAX * HDIM];  // fp16 mirror for gathers
__device__ __align__(256) float g_hB[NMAX * HDIM];    // fp32 gather output
__device__ float g_s[NMAX];
__device__ float g_d[NMAX];
__device__ int   g_cnt[NMAX + 1];     // histogram, later scatter cursor
__device__ int   g_offs[NMAX + 1];    // CSR row offsets (by dst)
__device__ int   g_csr[EMAX];         // src indices sorted by dst
__device__ float g_vnsum[NGROUP * HDIM];
// decoupled-lookback scan state
__device__ int g_tick;
__device__ int g_flag[256];
__device__ int g_aggval[256];
__device__ int g_incval[256];

// ---------------------------------------------------------------------------
// CSR build: zero -> histogram -> scan(lookback) -> scatter
// ---------------------------------------------------------------------------
__global__ void zero_kernel(int N) {
    int i = blockIdx.x * blockDim.x + threadIdx.x;
    if (i <= N) g_cnt[i] = 0;
    if (i < NGROUP * HDIM) g_vnsum[i] = 0.f;
    if (i < 256) g_flag[i] = 0;
    if (i == 0) g_tick = 0;
}

__global__ void hist_kernel(const int* __restrict__ ei, int E) {
    int e = blockIdx.x * blockDim.x + threadIdx.x;
    if (e < E) atomicAdd(&g_cnt[ei[E + e]], 1);
}

// single-pass exclusive scan of g_cnt with decoupled lookback.
// 1024 elements / block of 256 threads; writes g_offs and cursor g_cnt.
__global__ void scan_kernel(int N, int E) {
    __shared__ int wsum[8];
    __shared__ int bid_s, base_s;
    int t = threadIdx.x;
    if (t == 0) bid_s = atomicAdd(&g_tick, 1);
    __syncthreads();
    int bid = bid_s;
    int base = bid * 1024;
    int v[4]; int s = 0;
#pragma unroll
    for (int j = 0; j < 4; j++) {
        int idx = base + t * 4 + j;
        v[j] = (idx < N) ? g_cnt[idx] : 0;
        s += v[j];
    }
    int lane = t & 31, wid = t >> 5;
    int inc = s;
#pragma unroll
    for (int o = 1; o < 32; o <<= 1) {
        int y = __shfl_up_sync(0xffffffffu, inc, o);
        if (lane >= o) inc += y;
    }
    if (lane == 31) wsum[wid] = inc;
    __syncthreads();
    if (t < 8) {
        int x = wsum[t];
#pragma unroll
        for (int o = 1; o < 8; o <<= 1) {
            int y = __shfl_up_sync(0xffu, x, o);
            if (t >= o) x += y;
        }
        wsum[t] = x;
    }
    __syncthreads();
    if (t == 0) {
        int total = wsum[7];
        g_aggval[bid] = total;
        __threadfence();
        *(volatile int*)&g_flag[bid] = 1;
        int excl = 0;
        for (int j = bid - 1; j >= 0;) {
            int f;
            do { f = *(volatile int*)&g_flag[j]; } while (f == 0);
            if (f == 2) { excl += *(volatile int*)&g_incval[j]; break; }
            excl += *(volatile int*)&g_aggval[j];
            j--;
        }
        g_incval[bid] = excl + total;
        __threadfence();
        *(volatile int*)&g_flag[bid] = 2;
        base_s = excl;
    }
    __syncthreads();
    int excl = inc - s + (wid > 0 ? wsum[wid - 1] : 0) + base_s;
#pragma unroll
    for (int j = 0; j < 4; j++) {
        int idx = base + t * 4 + j;
        if (idx < N) {
            g_offs[idx] = excl;
            g_cnt[idx] = excl;   // scatter cursor
        }
        excl += v[j];
    }
    if (bid == 0 && t == 0) g_offs[N] = E;
}

__global__ void scatter_kernel(const int* __restrict__ ei, int E) {
    int e = blockIdx.x * blockDim.x + threadIdx.x;
    if (e >= E) return;
    int src = ei[e];
    int dst = ei[E + e];
    int pos = atomicAdd(&g_cnt[dst], 1);
    g_csr[pos] = src;
}

// ---------------------------------------------------------------------------
// Layer 0 linear: h = x(N,3) @ W0(3,64) -> g_h16; also s = h.as, d = h.ad
// ---------------------------------------------------------------------------
__global__ void lin0_kernel(const float* __restrict__ x,
                            const float* __restrict__ W0,
                            const float* __restrict__ as0,
                            const float* __restrict__ ad0, int N) {
    __shared__ float Ws[3 * 64];
    __shared__ float hs[64][65];
    int t = threadIdx.x;
    int c = t & 63, r = t >> 6;
    int n0 = blockIdx.x * 64;
    if (t < 192) Ws[t] = W0[t];
    __syncthreads();
#pragma unroll
    for (int i = 0; i < 16; i++) {
        int nl = r * 16 + i;
        int n = n0 + nl;
        float acc = 0.f;
        if (n < N) {
            float x0 = x[n * 3 + 0], x1 = x[n * 3 + 1], x2 = x[n * 3 + 2];
            acc = x0 * Ws[c] + x1 * Ws[64 + c] + x2 * Ws[128 + c];
            g_h16[n * 64 + c] = __float2half_rn(acc);
        }
        hs[nl][c] = acc;
    }
    __syncthreads();
    if (t < 64) {
        int n = n0 + t;
        if (n < N) {
            float sv = 0.f, dv = 0.f;
#pragma unroll
            for (int k = 0; k < 64; k++) {
                float hv = hs[t][k];
                sv += hv * as0[k];
                dv += hv * ad0[k];
            }
            g_s[n] = sv;
            g_d[n] = dv;
        }
    }
}

// ---------------------------------------------------------------------------
// Gather attention pass (g_h16 -> g_hB): one warp per dst node.
// EXACT copy of the 201.9us (R11) version: staged p + half-warp split
// (lanes 0-15 even staged edges, 16-31 odd; 8B/lane). Warp-uniform control.
// (max-shift skipped: softmax shift-invariant, logits are O(0.1))
// ---------------------------------------------------------------------------
__global__ void gather_kernel(const float* __restrict__ bias, int N) {
    __shared__ int2 stage[8][32];
    int w = (blockIdx.x * blockDim.x + threadIdx.x) >> 5;
    int lane = threadIdx.x & 31;
    int wl = threadIdx.x >> 5;
    if (w >= N) return;
    int dst = w;
    int l16 = lane & 15;
    int hi = lane >> 4;          // 0: even edges, 1: odd edges
    float dv = g_d[dst];
    // self loop
    float lg = g_s[dst] + dv;
    lg = lg > 0.f ? lg : 0.2f * lg;
    float pself = __expf(lg);
    float a0 = 0.f, a1 = 0.f, a2 = 0.f, a3 = 0.f;
    if (hi == 0) {
        uint2 r = *(const uint2*)(g_h16 + dst * 64 + l16 * 4);
        float2 fA = __half22float2(*(__half2*)&r.x);
        float2 fB = __half22float2(*(__half2*)&r.y);
        a0 = pself * fA.x; a1 = pself * fA.y;
        a2 = pself * fB.x; a3 = pself * fB.y;
    }
    float denl = (lane == 0) ? pself : 0.f;
    int e0 = g_offs[dst], e1 = g_offs[dst + 1];
    for (int base = e0; base < e1; base += 32) {
        int cnt = e1 - base;
        if (cnt > 32) cnt = 32;
        int idx = 0;
        float pv = 0.f;
        if (lane < cnt) {
            idx = g_csr[base + lane];
            float sv = g_s[idx];
            float l = sv + dv;
            l = l > 0.f ? l : 0.2f * l;
            pv = __expf(l);
        }
        denl += pv;
        stage[wl][lane] = make_int2(idx, __float_as_int(pv));
        __syncwarp();
        int j = 0;
        for (; j + 7 < cnt; j += 8) {     // 4 pairs = 8 edges per iter
            int2 v0 = stage[wl][j + hi];
            int2 v1 = stage[wl][j + 2 + hi];
            int2 v2 = stage[wl][j + 4 + hi];
            int2 v3 = stage[wl][j + 6 + hi];
            uint2 r0 = *(const uint2*)(g_h16 + v0.x * 64 + l16 * 4);
            uint2 r1 = *(const uint2*)(g_h16 + v1.x * 64 + l16 * 4);
            uint2 r2 = *(const uint2*)(g_h16 + v2.x * 64 + l16 * 4);
            uint2 r3 = *(const uint2*)(g_h16 + v3.x * 64 + l16 * 4);
            float p0 = __int_as_float(v0.y), p1 = __int_as_float(v1.y);
            float p2 = __int_as_float(v2.y), p3 = __int_as_float(v3.y);
            float2 fA, fB;
            fA = __half22float2(*(__half2*)&r0.x); fB = __half22float2(*(__half2*)&r0.y);
            a0 += p0 * fA.x; a1 += p0 * fA.y; a2 += p0 * fB.x; a3 += p0 * fB.y;
            fA = __half22float2(*(__half2*)&r1.x); fB = __half22float2(*(__half2*)&r1.y);
            a0 += p1 * fA.x; a1 += p1 * fA.y; a2 += p1 * fB.x; a3 += p1 * fB.y;
            fA = __half22float2(*(__half2*)&r2.x); fB = __half22float2(*(__half2*)&r2.y);
            a0 += p2 * fA.x; a1 += p2 * fA.y; a2 += p2 * fB.x; a3 += p2 * fB.y;
            fA = __half22float2(*(__half2*)&r3.x); fB = __half22float2(*(__half2*)&r3.y);
            a0 += p3 * fA.x; a1 += p3 * fA.y; a2 += p3 * fB.x; a3 += p3 * fB.y;
        }
        for (; j < cnt; j += 2) {         // pad entries have pv = 0
            int2 v = stage[wl][j + hi];
            uint2 r = *(const uint2*)(g_h16 + v.x * 64 + l16 * 4);
            float p = __int_as_float(v.y);
            float2 fA = __half22float2(*(__half2*)&r.x);
            float2 fB = __half22float2(*(__half2*)&r.y);
            a0 += p * fA.x; a1 += p * fA.y; a2 += p * fB.x; a3 += p * fB.y;
        }
        __syncwarp();
    }
    // merge the two halves (same columns)
    a0 += __shfl_xor_sync(0xffffffffu, a0, 16);
    a1 += __shfl_xor_sync(0xffffffffu, a1, 16);
    a2 += __shfl_xor_sync(0xffffffffu, a2, 16);
    a3 += __shfl_xor_sync(0xffffffffu, a3, 16);
#pragma unroll
    for (int o = 16; o >= 1; o >>= 1) denl += __shfl_xor_sync(0xffffffffu, denl, o);
    if (hi == 0) {
        float inv = 1.f / denl;
        float4 bv = *(const float4*)(bias + l16 * 4);
        float o0 = a0 * inv + bv.x;
        float o1 = a1 * inv + bv.y;
        float o2 = a2 * inv + bv.z;
        float o3 = a3 * inv + bv.w;
        o0 = o0 > 0.f ? o0 : 0.01f * o0;
        o1 = o1 > 0.f ? o1 : 0.01f * o1;
        o2 = o2 > 0.f ? o2 : 0.01f * o2;
        o3 = o3 > 0.f ? o3 : 0.01f * o3;
        *(float4*)(g_hB + dst * 64 + l16 * 4) = make_float4(o0, o1, o2, o3);
    }
}

// ---------------------------------------------------------------------------
// Tensor-core GEMM (g_hB -> g_h16): h = x(128,64) @ W(64,64) via
// mma.sync.m16n8k8.f32.f16.f16.f32. Block 256 = 8 warps x 16 nodes.
// ---------------------------------------------------------------------------
__global__ void fin_lin_kernel(const float* __restrict__ W,
                               const float* __restrict__ avs,
                               const float* __restrict__ avd, int N) {
    __shared__ __half xh[128][72];
    __shared__ __half Wt[64][72];
    __shared__ float as_sh[64], ad_sh[64];
    int t = threadIdx.x;
    int n0 = blockIdx.x * 128;
    // W -> fp16 transposed
#pragma unroll
    for (int j = 0; j < 16; j++) {
        int idx = j * 256 + t;
        int k = idx >> 6, n = idx & 63;
        Wt[n][k] = __float2half_rn(W[idx]);
    }
    if (t < 64) { as_sh[t] = avs[t]; ad_sh[t] = avd[t]; }
    // x (fp32 gather output) -> fp16 smem
#pragma unroll
    for (int j = 0; j < 8; j++) {
        int idx = j * 256 + t;            // float4 chunks over 128x64
        int nl = idx >> 4, c4 = (idx & 15) * 4;
        int n = n0 + nl;
        float4 v = (n < N) ? *(const float4*)(g_hB + (long long)n * 64 + c4)
                           : make_float4(0.f, 0.f, 0.f, 0.f);
        *(__half2*)&xh[nl][c4]     = __floats2half2_rn(v.x, v.y);
        *(__half2*)&xh[nl][c4 + 2] = __floats2half2_rn(v.z, v.w);
    }
    __syncthreads();

    int wid = t >> 5, lane = t & 31;
    int g = lane >> 2, tg = lane & 3;
    int nw = wid * 16;                     // warp's node base within block
    float acc[8][4];
#pragma unroll
    for (int i = 0; i < 8; i++)
#pragma unroll
        for (int j = 0; j < 4; j++) acc[i][j] = 0.f;

#pragma unroll
    for (int s = 0; s < 8; s++) {
        unsigned a0 = *(const unsigned*)&xh[nw + g][s * 8 + tg * 2];
        unsigned a1 = *(const unsigned*)&xh[nw + g + 8][s * 8 + tg * 2];
#pragma unroll
        for (int nt = 0; nt < 8; nt++) {
            unsigned b = *(const unsigned*)&Wt[nt * 8 + g][s * 8 + tg * 2];
            asm volatile(
                "mma.sync.aligned.m16n8k8.row.col.f32.f16.f16.f32 "
                "{%0,%1,%2,%3}, {%4,%5}, {%6}, {%0,%1,%2,%3};"
                : "+f"(acc[nt][0]), "+f"(acc[nt][1]),
                  "+f"(acc[nt][2]), "+f"(acc[nt][3])
                : "r"(a0), "r"(a1), "r"(b));
        }
    }

    // s/d dots from fp32 accumulators
    float ps0 = 0.f, ps1 = 0.f, pd0 = 0.f, pd1 = 0.f;
#pragma unroll
    for (int nt = 0; nt < 8; nt++) {
        float2 a = *(const float2*)&as_sh[nt * 8 + tg * 2];
        float2 d = *(const float2*)&ad_sh[nt * 8 + tg * 2];
        ps0 += acc[nt][0] * a.x + acc[nt][1] * a.y;
        ps1 += acc[nt][2] * a.x + acc[nt][3] * a.y;
        pd0 += acc[nt][0] * d.x + acc[nt][1] * d.y;
        pd1 += acc[nt][2] * d.x + acc[nt][3] * d.y;
    }
#pragma unroll
    for (int o = 1; o <= 2; o <<= 1) {
        ps0 += __shfl_xor_sync(0xffffffffu, ps0, o);
        ps1 += __shfl_xor_sync(0xffffffffu, ps1, o);
        pd0 += __shfl_xor_sync(0xffffffffu, pd0, o);
        pd1 += __shfl_xor_sync(0xffffffffu, pd1, o);
    }
    if (tg == 0) {
        int n1 = n0 + nw + g, n2 = n1 + 8;
        if (n1 < N) { g_s[n1] = ps0; g_d[n1] = pd0; }
        if (n2 < N) { g_s[n2] = ps1; g_d[n2] = pd1; }
    }

    // stage fp16 result into this warp's own xh rows, then vectorized copy out
#pragma unroll
    for (int nt = 0; nt < 8; nt++) {
        *(__half2*)&xh[nw + g][nt * 8 + tg * 2]     = __floats2half2_rn(acc[nt][0], acc[nt][1]);
        *(__half2*)&xh[nw + g + 8][nt * 8 + tg * 2] = __floats2half2_rn(acc[nt][2], acc[nt][3]);
    }
    __syncwarp();
#pragma unroll
    for (int j = 0; j < 4; j++) {
        int cid = j * 32 + lane;           // 128 uint4 chunks = 16 rows x 8
        int r = nw + (cid >> 3);
        int c = (cid & 7) * 8;
        uint4 v = *(const uint4*)&xh[r][c];
        int n = n0 + r;
        if (n < N) *(uint4*)(g_h16 + (long long)n * 64 + c) = v;
    }
}

// ---------------------------------------------------------------------------
// Final stage (reads g_hB): out1 = h @ out_w + out_b (2x5 register tile,
// 256 threads); vn run-length pooling (batch sorted). 128 nodes/block.
// ---------------------------------------------------------------------------
__global__ void fin_last_kernel(const float* __restrict__ out_w,
                                const float* __restrict__ out_b,
                                const int* __restrict__ batch,
                                float* __restrict__ out1, int N) {
    __shared__ float hs[128][65];
    __shared__ float ow[64][20];
    __shared__ float ob[20];
    __shared__ int bsh[128];
    int t = threadIdx.x;
    int n0 = blockIdx.x * 128;
    for (int idx = t; idx < 64 * 20; idx += 256) ow[idx / 20][idx % 20] = out_w[idx];
    if (t < 20) ob[t] = out_b[t];
#pragma unroll
    for (int j = 0; j < 32; j++) {
        int idx = j * 256 + t;
        int nl = idx >> 6, c = idx & 63;
        int n = n0 + nl;
        hs[nl][c] = (n < N) ? g_hB[n * 64 + c] : 0.f;
    }
    if (t < 128) {
        int n = n0 + t;
        bsh[t] = (n < N) ? batch[n] : -1;
    }
    __syncthreads();
    int ngq = t >> 2, cgq = t & 3;   // 64 node groups x 4 col groups
    float acc[2][5];
#pragma unroll
    for (int i = 0; i < 2; i++)
#pragma unroll
        for (int j = 0; j < 5; j++) acc[i][j] = ob[cgq * 5 + j];
#pragma unroll 8
    for (int k = 0; k < 64; k++) {
        float wv[5];
#pragma unroll
        for (int j = 0; j < 5; j++) wv[j] = ow[k][cgq * 5 + j];
#pragma unroll
        for (int i = 0; i < 2; i++) {
            float hv = hs[ngq * 2 + i][k];
#pragma unroll
            for (int j = 0; j < 5; j++) acc[i][j] += hv * wv[j];
        }
    }
#pragma unroll
    for (int i = 0; i < 2; i++) {
        int n = n0 + ngq * 2 + i;
        if (n < N) {
#pragma unroll
            for (int j = 0; j < 5; j++) out1[n * 20 + cgq * 5 + j] = acc[i][j];
        }
    }
    // vn pooling: threads 0..63 own one column each, run-length over block
    if (t < 64) {
        int nend = N - n0;
        if (nend > 128) nend = 128;
        if (nend > 0) {
            int curg = bsh[0];
            float run = 0.f;
            for (int nl = 0; nl < nend; nl++) {
                int g = bsh[nl];
                if (g != curg) {
                    atomicAdd(&g_vnsum[curg * 64 + t], run);
                    run = 0.f;
                    curg = g;
                }
                run += hs[nl][t];
            }
            atomicAdd(&g_vnsum[curg * 64 + t], run);
        }
    }
}

// ---------------------------------------------------------------------------
// Virtual-node MLP head: 4 layers on [8,64] -> [8,20]. One block.
// ---------------------------------------------------------------------------
__global__ void vn_mlp_kernel(const float* __restrict__ vn_emb0,
                              const float* __restrict__ w1, const float* __restrict__ bb1,
                              const float* __restrict__ w2, const float* __restrict__ bb2,
                              const float* __restrict__ w3, const float* __restrict__ bb3,
                              const float* __restrict__ w4, const float* __restrict__ bb4,
                              float* __restrict__ outvn) {
    __shared__ float a[NGROUP][64], tmp[NGROUP][64];
    int t = threadIdx.x;  // 512
    int g = t >> 6, c = t & 63;
    a[g][c] = g_vnsum[g * 64 + c] + vn_emb0[c];
    __syncthreads();
    float s = bb1[c];
    for (int k = 0; k < 64; k++) s += a[g][k] * w1[k * 64 + c];
    tmp[g][c] = fmaxf(s, 0.f);
    __syncthreads();
    s = bb2[c];
    for (int k = 0; k < 64; k++) s += tmp[g][k] * w2[k * 64 + c];
    a[g][c] = fmaxf(s, 0.f);
    __syncthreads();
    s = bb3[c];
    for (int k = 0; k < 64; k++) s += a[g][k] * w3[k * 64 + c];
    tmp[g][c] = fmaxf(s, 0.f);
    __syncthreads();
    if (c < 20) {
        s = bb4[c];
        for (int k = 0; k < 64; k++) s += tmp[g][k] * w4[k * 20 + c];
        outvn[g * 20 + c] = fmaxf(s, 0.f);
    }
}

// ---------------------------------------------------------------------------
extern "C" void kernel_launch(void* const* d_in, const int* in_sizes, int n_in,
                              void* d_out, int out_size) {
    const float* x      = (const float*)d_in[0];
    const int*   ei     = (const int*)d_in[1];
    const int*   batch  = (const int*)d_in[2];
    const float* W0     = (const float*)d_in[3];
    const float* as0    = (const float*)d_in[4];
    const float* ad0    = (const float*)d_in[5];
    const float* b0     = (const float*)d_in[6];
    const float* W1     = (const float*)d_in[7];
    const float* as1    = (const float*)d_in[8];
    const float* ad1    = (const float*)d_in[9];
    const float* b1     = (const float*)d_in[10];
    const float* W2     = (const float*)d_in[11];
    const float* as2    = (const float*)d_in[12];
    const float* ad2    = (const float*)d_in[13];
    const float* b2     = (const float*)d_in[14];
    const float* vn_emb0= (const float*)d_in[15];
    const float* m1_w1  = (const float*)d_in[16];
    const float* m1_b1  = (const float*)d_in[17];
    const float* m1_w2  = (const float*)d_in[18];
    const float* m1_b2  = (const float*)d_in[19];
    const float* mf_w1  = (const float*)d_in[20];
    const float* mf_b1  = (const float*)d_in[21];
    const float* mf_w2  = (const float*)d_in[22];
    const float* mf_b2  = (const float*)d_in[23];
    const float* out_w  = (const float*)d_in[24];
    const float* out_b  = (const float*)d_in[25];

    int N = in_sizes[0] / 3;
    int E = in_sizes[1] / 2;
    float* out1 = (float*)d_out;
    float* outvn = out1 + (long long)N * 20;

    int nblk64  = (N + 63) / 64;
    int nblk128 = (N + 127) / 128;
    int eblk    = (E + 255) / 256;
    int NB      = (N + 1023) / 1024;
    int gblk    = (N * 32 + 255) / 256;   // one full warp per node

    // CSR build (graph shared by all 3 layers)
    zero_kernel<<<(N + 256) / 256, 256>>>(N);
    hist_kernel<<<eblk, 256>>>(ei, E);
    scan_kernel<<<NB, 256>>>(N, E);
    scatter_kernel<<<eblk, 256>>>(ei, E);

    // GNN layers (ping-pong: lin0 -> h16, gather h16->B, fin_lin B->h16)
    lin0_kernel<<<nblk64, 256>>>(x, W0, as0, ad0, N);
    gather_kernel<<<gblk, 256>>>(b0, N);
    fin_lin_kernel<<<nblk128, 256>>>(W1, as1, ad1, N);
    gather_kernel<<<gblk, 256>>>(b1, N);
    fin_lin_kernel<<<nblk128, 256>>>(W2, as2, ad2, N);
    gather_kernel<<<gblk, 256>>>(b2, N);

    // heads (read g_hB)
    fin_last_kernel<<<nblk128, 256>>>(out_w, out_b, batch, out1, N);
    vn_mlp_kernel<<<1, 512>>>(vn_emb0, m1_w1, m1_b1, m1_w2, m1_b2,
                              mf_w1, mf_b1, mf_w2, mf_b2, outvn);
}

// round 16
// speedup vs baseline: 1.0700x; 1.0513x over previous
#include <cuda_runtime.h>
#include <cuda_fp16.h>

#define NMAX 100000
#define EMAX 1600000
#define HDIM 64
#define NGROUP 8

// ---------------- device scratch (no allocation allowed) --------------------
__device__ __align__(256) __half g_h16[NMAX * HDIM];  // fp16 mirror for gathers
__device__ __align__(256) float g_hB[NMAX * HDIM];    // fp32 gather output
__device__ float g_s[NMAX];
__device__ float g_d[NMAX];
__device__ int   g_cnt[NMAX + 1];     // histogram, later scatter cursor
__device__ int   g_offs[NMAX + 1];    // CSR row offsets (by dst)
__device__ int   g_blksum[256];
__device__ int   g_csr[EMAX];         // src indices sorted by dst
__device__ float g_vnsum[NGROUP * HDIM];

// ---------------------------------------------------------------------------
// CSR build: zero -> histogram -> scanA -> scanC(+blk prefix) -> scatter
// ---------------------------------------------------------------------------
__global__ void zero_kernel(int N) {
    int i = blockIdx.x * blockDim.x + threadIdx.x;
    if (i <= N) g_cnt[i] = 0;
    if (i < NGROUP * HDIM) g_vnsum[i] = 0.f;
}

// 4 edges per thread for ILP (scatter-atomic histogram)
__global__ void hist_kernel(const int* __restrict__ ei, int E) {
    int base = (blockIdx.x * blockDim.x + threadIdx.x) * 4;
    if (base >= E) return;
    if (base + 3 < E && ((E & 3) == 0)) {
        int4 d4 = *(const int4*)(ei + E + base);
        atomicAdd(&g_cnt[d4.x], 1);
        atomicAdd(&g_cnt[d4.y], 1);
        atomicAdd(&g_cnt[d4.z], 1);
        atomicAdd(&g_cnt[d4.w], 1);
    } else {
        int end = base + 4 < E ? base + 4 : E;
        for (int e = base; e < end; e++) atomicAdd(&g_cnt[ei[E + e]], 1);
    }
}

// per-block exclusive scan of g_cnt (1024 elements / block of 256 threads)
__global__ void scanA_kernel(int N) {
    __shared__ int wsum[8];
    int t = threadIdx.x;
    int base = blockIdx.x * 1024;
    int v[4]; int s = 0;
#pragma unroll
    for (int j = 0; j < 4; j++) {
        int idx = base + t * 4 + j;
        v[j] = (idx < N) ? g_cnt[idx] : 0;
        s += v[j];
    }
    int lane = t & 31, wid = t >> 5;
    int inc = s;
#pragma unroll
    for (int o = 1; o < 32; o <<= 1) {
        int y = __shfl_up_sync(0xffffffffu, inc, o);
        if (lane >= o) inc += y;
    }
    if (lane == 31) wsum[wid] = inc;
    __syncthreads();
    if (t < 8) {
        int x = wsum[t];
#pragma unroll
        for (int o = 1; o < 8; o <<= 1) {
            int y = __shfl_up_sync(0xffu, x, o);
            if (t >= o) x += y;
        }
        wsum[t] = x;
    }
    __syncthreads();
    int excl = inc - s + (wid > 0 ? wsum[wid - 1] : 0);
#pragma unroll
    for (int j = 0; j < 4; j++) {
        int idx = base + t * 4 + j;
        if (idx < N) g_offs[idx] = excl;
        excl += v[j];
    }
    if (t == 255) g_blksum[blockIdx.x] = wsum[7];
}

// adds cross-block prefix (computed in-kernel by warp 0) and finalizes offsets
__global__ void scanC_kernel(int N, int E) {
    __shared__ int sbase;
    int myblk = (blockIdx.x * 256) >> 10;
    if (threadIdx.x < 32) {
        int acc = 0;
        for (int j = threadIdx.x; j < myblk; j += 32) acc += g_blksum[j];
#pragma unroll
        for (int o = 16; o >= 1; o >>= 1) acc += __shfl_xor_sync(0xffffffffu, acc, o);
        if (threadIdx.x == 0) sbase = acc;
    }
    __syncthreads();
    int i = blockIdx.x * 256 + threadIdx.x;
    if (i < N) {
        int o = g_offs[i] + sbase;
        g_offs[i] = o;
        g_cnt[i] = o;   // scatter cursor
    }
    if (i == 0) g_offs[N] = E;
}

// 4 edges per thread for ILP (4 independent atomic+store chains)
__global__ void scatter_kernel(const int* __restrict__ ei, int E) {
    int base = (blockIdx.x * blockDim.x + threadIdx.x) * 4;
    if (base >= E) return;
    if (base + 3 < E && ((E & 3) == 0)) {
        int4 s4 = *(const int4*)(ei + base);
        int4 d4 = *(const int4*)(ei + E + base);
        int p0 = atomicAdd(&g_cnt[d4.x], 1);
        int p1 = atomicAdd(&g_cnt[d4.y], 1);
        int p2 = atomicAdd(&g_cnt[d4.z], 1);
        int p3 = atomicAdd(&g_cnt[d4.w], 1);
        g_csr[p0] = s4.x;
        g_csr[p1] = s4.y;
        g_csr[p2] = s4.z;
        g_csr[p3] = s4.w;
    } else {
        int end = base + 4 < E ? base + 4 : E;
        for (int e = base; e < end; e++) {
            int pos = atomicAdd(&g_cnt[ei[E + e]], 1);
            g_csr[pos] = ei[e];
        }
    }
}

// ---------------------------------------------------------------------------
// Layer 0 linear: h = x(N,3) @ W0(3,64) -> g_h16; also s = h.as, d = h.ad
// ---------------------------------------------------------------------------
__global__ void lin0_kernel(const float* __restrict__ x,
                            const float* __restrict__ W0,
                            const float* __restrict__ as0,
                            const float* __restrict__ ad0, int N) {
    __shared__ float Ws[3 * 64];
    __shared__ float hs[64][65];
    int t = threadIdx.x;
    int c = t & 63, r = t >> 6;
    int n0 = blockIdx.x * 64;
    if (t < 192) Ws[t] = W0[t];
    __syncthreads();
#pragma unroll
    for (int i = 0; i < 16; i++) {
        int nl = r * 16 + i;
        int n = n0 + nl;
        float acc = 0.f;
        if (n < N) {
            float x0 = x[n * 3 + 0], x1 = x[n * 3 + 1], x2 = x[n * 3 + 2];
            acc = x0 * Ws[c] + x1 * Ws[64 + c] + x2 * Ws[128 + c];
            g_h16[n * 64 + c] = __float2half_rn(acc);
        }
        hs[nl][c] = acc;
    }
    __syncthreads();
    if (t < 64) {
        int n = n0 + t;
        if (n < N) {
            float sv = 0.f, dv = 0.f;
#pragma unroll
            for (int k = 0; k < 64; k++) {
                float hv = hs[t][k];
                sv += hv * as0[k];
                dv += hv * ad0[k];
            }
            g_s[n] = sv;
            g_d[n] = dv;
        }
    }
}

// ---------------------------------------------------------------------------
// Gather attention pass (g_h16 -> g_hB): one warp per dst node.
// EXACT copy of the 201.9us (R11) version: staged p + half-warp split
// (lanes 0-15 even staged edges, 16-31 odd; 8B/lane). Warp-uniform control.
// (max-shift skipped: softmax shift-invariant, logits are O(0.1))
// ---------------------------------------------------------------------------
__global__ void gather_kernel(const float* __restrict__ bias, int N) {
    __shared__ int2 stage[8][32];
    int w = (blockIdx.x * blockDim.x + threadIdx.x) >> 5;
    int lane = threadIdx.x & 31;
    int wl = threadIdx.x >> 5;
    if (w >= N) return;
    int dst = w;
    int l16 = lane & 15;
    int hi = lane >> 4;          // 0: even edges, 1: odd edges
    float dv = g_d[dst];
    // self loop
    float lg = g_s[dst] + dv;
    lg = lg > 0.f ? lg : 0.2f * lg;
    float pself = __expf(lg);
    float a0 = 0.f, a1 = 0.f, a2 = 0.f, a3 = 0.f;
    if (hi == 0) {
        uint2 r = *(const uint2*)(g_h16 + dst * 64 + l16 * 4);
        float2 fA = __half22float2(*(__half2*)&r.x);
        float2 fB = __half22float2(*(__half2*)&r.y);
        a0 = pself * fA.x; a1 = pself * fA.y;
        a2 = pself * fB.x; a3 = pself * fB.y;
    }
    float denl = (lane == 0) ? pself : 0.f;
    int e0 = g_offs[dst], e1 = g_offs[dst + 1];
    for (int base = e0; base < e1; base += 32) {
        int cnt = e1 - base;
        if (cnt > 32) cnt = 32;
        int idx = 0;
        float pv = 0.f;
        if (lane < cnt) {
            idx = g_csr[base + lane];
            float sv = g_s[idx];
            float l = sv + dv;
            l = l > 0.f ? l : 0.2f * l;
            pv = __expf(l);
        }
        denl += pv;
        stage[wl][lane] = make_int2(idx, __float_as_int(pv));
        __syncwarp();
        int j = 0;
        for (; j + 7 < cnt; j += 8) {     // 4 pairs = 8 edges per iter
            int2 v0 = stage[wl][j + hi];
            int2 v1 = stage[wl][j + 2 + hi];
            int2 v2 = stage[wl][j + 4 + hi];
            int2 v3 = stage[wl][j + 6 + hi];
            uint2 r0 = *(const uint2*)(g_h16 + v0.x * 64 + l16 * 4);
            uint2 r1 = *(const uint2*)(g_h16 + v1.x * 64 + l16 * 4);
            uint2 r2 = *(const uint2*)(g_h16 + v2.x * 64 + l16 * 4);
            uint2 r3 = *(const uint2*)(g_h16 + v3.x * 64 + l16 * 4);
            float p0 = __int_as_float(v0.y), p1 = __int_as_float(v1.y);
            float p2 = __int_as_float(v2.y), p3 = __int_as_float(v3.y);
            float2 fA, fB;
            fA = __half22float2(*(__half2*)&r0.x); fB = __half22float2(*(__half2*)&r0.y);
            a0 += p0 * fA.x; a1 += p0 * fA.y; a2 += p0 * fB.x; a3 += p0 * fB.y;
            fA = __half22float2(*(__half2*)&r1.x); fB = __half22float2(*(__half2*)&r1.y);
            a0 += p1 * fA.x; a1 += p1 * fA.y; a2 += p1 * fB.x; a3 += p1 * fB.y;
            fA = __half22float2(*(__half2*)&r2.x); fB = __half22float2(*(__half2*)&r2.y);
            a0 += p2 * fA.x; a1 += p2 * fA.y; a2 += p2 * fB.x; a3 += p2 * fB.y;
            fA = __half22float2(*(__half2*)&r3.x); fB = __half22float2(*(__half2*)&r3.y);
            a0 += p3 * fA.x; a1 += p3 * fA.y; a2 += p3 * fB.x; a3 += p3 * fB.y;
        }
        for (; j < cnt; j += 2) {         // pad entries have pv = 0
            int2 v = stage[wl][j + hi];
            uint2 r = *(const uint2*)(g_h16 + v.x * 64 + l16 * 4);
            float p = __int_as_float(v.y);
            float2 fA = __half22float2(*(__half2*)&r.x);
            float2 fB = __half22float2(*(__half2*)&r.y);
            a0 += p * fA.x; a1 += p * fA.y; a2 += p * fB.x; a3 += p * fB.y;
        }
        __syncwarp();
    }
    // merge the two halves (same columns)
    a0 += __shfl_xor_sync(0xffffffffu, a0, 16);
    a1 += __shfl_xor_sync(0xffffffffu, a1, 16);
    a2 += __shfl_xor_sync(0xffffffffu, a2, 16);
    a3 += __shfl_xor_sync(0xffffffffu, a3, 16);
#pragma unroll
    for (int o = 16; o >= 1; o >>= 1) denl += __shfl_xor_sync(0xffffffffu, denl, o);
    if (hi == 0) {
        float inv = 1.f / denl;
        float4 bv = *(const float4*)(bias + l16 * 4);
        float o0 = a0 * inv + bv.x;
        float o1 = a1 * inv + bv.y;
        float o2 = a2 * inv + bv.z;
        float o3 = a3 * inv + bv.w;
        o0 = o0 > 0.f ? o0 : 0.01f * o0;
        o1 = o1 > 0.f ? o1 : 0.01f * o1;
        o2 = o2 > 0.f ? o2 : 0.01f * o2;
        o3 = o3 > 0.f ? o3 : 0.01f * o3;
        *(float4*)(g_hB + dst * 64 + l16 * 4) = make_float4(o0, o1, o2, o3);
    }
}

// ---------------------------------------------------------------------------
// Tensor-core GEMM (g_hB -> g_h16): h = x(128,64) @ W(64,64) via
// mma.sync.m16n8k8.f32.f16.f16.f32. Block 256 = 8 warps x 16 nodes.
// ---------------------------------------------------------------------------
__global__ void fin_lin_kernel(const float* __restrict__ W,
                               const float* __restrict__ avs,
                               const float* __restrict__ avd, int N) {
    __shared__ __half xh[128][72];
    __shared__ __half Wt[64][72];
    __shared__ float as_sh[64], ad_sh[64];
    int t = threadIdx.x;
    int n0 = blockIdx.x * 128;
    // W -> fp16 transposed
#pragma unroll
    for (int j = 0; j < 16; j++) {
        int idx = j * 256 + t;
        int k = idx >> 6, n = idx & 63;
        Wt[n][k] = __float2half_rn(W[idx]);
    }
    if (t < 64) { as_sh[t] = avs[t]; ad_sh[t] = avd[t]; }
    // x (fp32 gather output) -> fp16 smem
#pragma unroll
    for (int j = 0; j < 8; j++) {
        int idx = j * 256 + t;            // float4 chunks over 128x64
        int nl = idx >> 4, c4 = (idx & 15) * 4;
        int n = n0 + nl;
        float4 v = (n < N) ? *(const float4*)(g_hB + (long long)n * 64 + c4)
                           : make_float4(0.f, 0.f, 0.f, 0.f);
        *(__half2*)&xh[nl][c4]     = __floats2half2_rn(v.x, v.y);
        *(__half2*)&xh[nl][c4 + 2] = __floats2half2_rn(v.z, v.w);
    }
    __syncthreads();

    int wid = t >> 5, lane = t & 31;
    int g = lane >> 2, tg = lane & 3;
    int nw = wid * 16;                     // warp's node base within block
    float acc[8][4];
#pragma unroll
    for (int i = 0; i < 8; i++)
#pragma unroll
        for (int j = 0; j < 4; j++) acc[i][j] = 0.f;

#pragma unroll
    for (int s = 0; s < 8; s++) {
        unsigned a0 = *(const unsigned*)&xh[nw + g][s * 8 + tg * 2];
        unsigned a1 = *(const unsigned*)&xh[nw + g + 8][s * 8 + tg * 2];
#pragma unroll
        for (int nt = 0; nt < 8; nt++) {
            unsigned b = *(const unsigned*)&Wt[nt * 8 + g][s * 8 + tg * 2];
            asm volatile(
                "mma.sync.aligned.m16n8k8.row.col.f32.f16.f16.f32 "
                "{%0,%1,%2,%3}, {%4,%5}, {%6}, {%0,%1,%2,%3};"
                : "+f"(acc[nt][0]), "+f"(acc[nt][1]),
                  "+f"(acc[nt][2]), "+f"(acc[nt][3])
                : "r"(a0), "r"(a1), "r"(b));
        }
    }

    // s/d dots from fp32 accumulators
    float ps0 = 0.f, ps1 = 0.f, pd0 = 0.f, pd1 = 0.f;
#pragma unroll
    for (int nt = 0; nt < 8; nt++) {
        float2 a = *(const float2*)&as_sh[nt * 8 + tg * 2];
        float2 d = *(const float2*)&ad_sh[nt * 8 + tg * 2];
        ps0 += acc[nt][0] * a.x + acc[nt][1] * a.y;
        ps1 += acc[nt][2] * a.x + acc[nt][3] * a.y;
        pd0 += acc[nt][0] * d.x + acc[nt][1] * d.y;
        pd1 += acc[nt][2] * d.x + acc[nt][3] * d.y;
    }
#pragma unroll
    for (int o = 1; o <= 2; o <<= 1) {
        ps0 += __shfl_xor_sync(0xffffffffu, ps0, o);
        ps1 += __shfl_xor_sync(0xffffffffu, ps1, o);
        pd0 += __shfl_xor_sync(0xffffffffu, pd0, o);
        pd1 += __shfl_xor_sync(0xffffffffu, pd1, o);
    }
    if (tg == 0) {
        int n1 = n0 + nw + g, n2 = n1 + 8;
        if (n1 < N) { g_s[n1] = ps0; g_d[n1] = pd0; }
        if (n2 < N) { g_s[n2] = ps1; g_d[n2] = pd1; }
    }

    // stage fp16 result into this warp's own xh rows, then vectorized copy out
#pragma unroll
    for (int nt = 0; nt < 8; nt++) {
        *(__half2*)&xh[nw + g][nt * 8 + tg * 2]     = __floats2half2_rn(acc[nt][0], acc[nt][1]);
        *(__half2*)&xh[nw + g + 8][nt * 8 + tg * 2] = __floats2half2_rn(acc[nt][2], acc[nt][3]);
    }
    __syncwarp();
#pragma unroll
    for (int j = 0; j < 4; j++) {
        int cid = j * 32 + lane;           // 128 uint4 chunks = 16 rows x 8
        int r = nw + (cid >> 3);
        int c = (cid & 7) * 8;
        uint4 v = *(const uint4*)&xh[r][c];
        int n = n0 + r;
        if (n < N) *(uint4*)(g_h16 + (long long)n * 64 + c) = v;
    }
}

// ---------------------------------------------------------------------------
// Final stage (reads g_hB): out1 = h @ out_w + out_b (4x5 register tile);
// vn run-length pooling (batch sorted). Block: 128 nodes, 128 threads.
// ---------------------------------------------------------------------------
__global__ void fin_last_kernel(const float* __restrict__ out_w,
                                const float* __restrict__ out_b,
                                const int* __restrict__ batch,
                                float* __restrict__ out1, int N) {
    __shared__ float hs[128][65];
    __shared__ float ow[64][20];
    __shared__ float ob[20];
    __shared__ int bsh[128];
    int t = threadIdx.x;
    int n0 = blockIdx.x * 128;
    for (int idx = t; idx < 64 * 20; idx += 128) ow[idx / 20][idx % 20] = out_w[idx];
    if (t < 20) ob[t] = out_b[t];
#pragma unroll
    for (int j = 0; j < 64; j++) {
        int idx = j * 128 + t;
        int nl = idx >> 6, c = idx & 63;
        int n = n0 + nl;
        hs[nl][c] = (n < N) ? g_hB[n * 64 + c] : 0.f;
    }
    {
        int n = n0 + t;
        bsh[t] = (n < N) ? batch[n] : -1;
    }
    __syncthreads();
    int ngq = t >> 2, cgq = t & 3;   // 32 node groups x 4 col groups
    float acc[4][5];
#pragma unroll
    for (int i = 0; i < 4; i++)
#pragma unroll
        for (int j = 0; j < 5; j++) acc[i][j] = ob[cgq * 5 + j];
#pragma unroll 8
    for (int k = 0; k < 64; k++) {
        float wv[5];
#pragma unroll
        for (int j = 0; j < 5; j++) wv[j] = ow[k][cgq * 5 + j];
#pragma unroll
        for (int i = 0; i < 4; i++) {
            float hv = hs[ngq * 4 + i][k];
#pragma unroll
            for (int j = 0; j < 5; j++) acc[i][j] += hv * wv[j];
        }
    }
#pragma unroll
    for (int i = 0; i < 4; i++) {
        int n = n0 + ngq * 4 + i;
        if (n < N) {
#pragma unroll
            for (int j = 0; j < 5; j++) out1[n * 20 + cgq * 5 + j] = acc[i][j];
        }
    }
    // vn pooling: threads 0..63 own one column each, run-length over block
    if (t < 64) {
        int nend = N - n0;
        if (nend > 128) nend = 128;
        if (nend > 0) {
            int curg = bsh[0];
            float run = 0.f;
            for (int nl = 0; nl < nend; nl++) {
                int g = bsh[nl];
                if (g != curg) {
                    atomicAdd(&g_vnsum[curg * 64 + t], run);
                    run = 0.f;
                    curg = g;
                }
                run += hs[nl][t];
            }
            atomicAdd(&g_vnsum[curg * 64 + t], run);
        }
    }
}

// ---------------------------------------------------------------------------
// Virtual-node MLP head: 4 layers on [8,64] -> [8,20]. One block.
// ---------------------------------------------------------------------------
__global__ void vn_mlp_kernel(const float* __restrict__ vn_emb0,
                              const float* __restrict__ w1, const float* __restrict__ bb1,
                              const float* __restrict__ w2, const float* __restrict__ bb2,
                              const float* __restrict__ w3, const float* __restrict__ bb3,
                              const float* __restrict__ w4, const float* __restrict__ bb4,
                              float* __restrict__ outvn) {
    __shared__ float a[NGROUP][64], tmp[NGROUP][64];
    int t = threadIdx.x;  // 512
    int g = t >> 6, c = t & 63;
    a[g][c] = g_vnsum[g * 64 + c] + vn_emb0[c];
    __syncthreads();
    float s = bb1[c];
    for (int k = 0; k < 64; k++) s += a[g][k] * w1[k * 64 + c];
    tmp[g][c] = fmaxf(s, 0.f);
    __syncthreads();
    s = bb2[c];
    for (int k = 0; k < 64; k++) s += tmp[g][k] * w2[k * 64 + c];
    a[g][c] = fmaxf(s, 0.f);
    __syncthreads();
    s = bb3[c];
    for (int k = 0; k < 64; k++) s += a[g][k] * w3[k * 64 + c];
    tmp[g][c] = fmaxf(s, 0.f);
    __syncthreads();
    if (c < 20) {
        s = bb4[c];
        for (int k = 0; k < 64; k++) s += tmp[g][k] * w4[k * 20 + c];
        outvn[g * 20 + c] = fmaxf(s, 0.f);
    }
}

// ---------------------------------------------------------------------------
extern "C" void kernel_launch(void* const* d_in, const int* in_sizes, int n_in,
                              void* d_out, int out_size) {
    const float* x      = (const float*)d_in[0];
    const int*   ei     = (const int*)d_in[1];
    const int*   batch  = (const int*)d_in[2];
    const float* W0     = (const float*)d_in[3];
    const float* as0    = (const float*)d_in[4];
    const float* ad0    = (const float*)d_in[5];
    const float* b0     = (const float*)d_in[6];
    const float* W1     = (const float*)d_in[7];
    const float* as1    = (const float*)d_in[8];
    const float* ad1    = (const float*)d_in[9];
    const float* b1     = (const float*)d_in[10];
    const float* W2     = (const float*)d_in[11];
    const float* as2    = (const float*)d_in[12];
    const float* ad2    = (const float*)d_in[13];
    const float* b2     = (const float*)d_in[14];
    const float* vn_emb0= (const float*)d_in[15];
    const float* m1_w1  = (const float*)d_in[16];
    const float* m1_b1  = (const float*)d_in[17];
    const float* m1_w2  = (const float*)d_in[18];
    const float* m1_b2  = (const float*)d_in[19];
    const float* mf_w1  = (const float*)d_in[20];
    const float* mf_b1  = (const float*)d_in[21];
    const float* mf_w2  = (const float*)d_in[22];
    const float* mf_b2  = (const float*)d_in[23];
    const float* out_w  = (const float*)d_in[24];
    const float* out_b  = (const float*)d_in[25];

    int N = in_sizes[0] / 3;
    int E = in_sizes[1] / 2;
    float* out1 = (float*)d_out;
    float* outvn = out1 + (long long)N * 20;

    int nblk64  = (N + 63) / 64;
    int nblk128 = (N + 127) / 128;
    int eblk4   = (E + 1023) / 1024;      // 4 edges per thread
    int NB      = (N + 1023) / 1024;
    int gblk    = (N * 32 + 255) / 256;   // one full warp per node

    // CSR build (graph shared by all 3 layers)
    zero_kernel<<<(N + 256) / 256, 256>>>(N);
    hist_kernel<<<eblk4, 256>>>(ei, E);
    scanA_kernel<<<NB, 256>>>(N);
    scanC_kernel<<<(N + 255) / 256, 256>>>(N, E);
    scatter_kernel<<<eblk4, 256>>>(ei, E);

    // GNN layers (ping-pong: lin0 -> h16, gather h16->B, fin_lin B->h16)
    lin0_kernel<<<nblk64, 256>>>(x, W0, as0, ad0, N);
    gather_kernel<<<gblk, 256>>>(b0, N);
    fin_lin_kernel<<<nblk128, 256>>>(W1, as1, ad1, N);
    gather_kernel<<<gblk, 256>>>(b1, N);
    fin_lin_kernel<<<nblk128, 256>>>(W2, as2, ad2, N);
    gather_kernel<<<gblk, 256>>>(b2, N);

    // heads (read g_hB)
    fin_last_kernel<<<nblk128, 128>>>(out_w, out_b, batch, out1, N);
    vn_mlp_kernel<<<1, 512>>>(vn_emb0, m1_w1, m1_b1, m1_w2, m1_b2,
                              mf_w1, mf_b1, mf_w2, mf_b2, outvn);
}